// round 4
// baseline (speedup 1.0000x reference)
#include <cuda_runtime.h>
#include <cstdint>
#include <cstddef>

#define DEVINL __device__ __forceinline__

constexpr int Bb   = 8;
constexpr int NSEQ = 1024;
constexpr int Dd   = 768;
constexpr int Hh   = 12;
constexpr int HD   = 64;
constexpr int Mrows = Bb * NSEQ;   // 8192

// ---------------- scratch (allocation-free rule: __device__ globals) ----------
__device__ float g_qh[(size_t)Bb * Hh * NSEQ * HD];   // [B,H,N,64]
__device__ float g_kh[(size_t)Bb * Hh * NSEQ * HD];
__device__ float g_vh[(size_t)Bb * Hh * NSEQ * HD];
__device__ float g_ao[(size_t)Mrows * Dd];            // attention out [B,N,D]

// ---------------- helpers ------------------------------------------------------
DEVINL uint32_t f2tf32(float x) {
    uint32_t r;
    asm("cvt.rna.tf32.f32 %0, %1;" : "=r"(r) : "f"(x));
    return r;
}

// exp(x) for x <= 0, FMA-pipe only (no MUFU). Max rel err ~2.4e-6.
// exp(x) = 2^(x*log2e); n = rint(y), f = y-n in [-0.5,0.5]; 2^f by deg-5 poly.
DEVINL float fexp(float x) {
    float y = fmaxf(x * 1.4426950408889634f, -126.0f);
    float n = rintf(y);
    float f = y - n;
    float p =            1.3333558146e-3f;
    p = fmaf(p, f, 9.6181291076e-3f);
    p = fmaf(p, f, 5.5504108665e-2f);
    p = fmaf(p, f, 2.4022650696e-1f);
    p = fmaf(p, f, 6.9314718056e-1f);
    p = fmaf(p, f, 1.0f);
    return p * __int_as_float(((int)n + 127) << 23);
}

DEVINL void mma_tf32(float d[4], const uint32_t a[4], const uint32_t b[2], const float c[4]) {
    asm("mma.sync.aligned.m16n8k8.row.col.f32.tf32.tf32.f32 "
        "{%0,%1,%2,%3}, {%4,%5,%6,%7}, {%8,%9}, {%10,%11,%12,%13};"
        : "=f"(d[0]), "=f"(d[1]), "=f"(d[2]), "=f"(d[3])
        : "r"(a[0]), "r"(a[1]), "r"(a[2]), "r"(a[3]),
          "r"(b[0]), "r"(b[1]),
          "f"(c[0]), "f"(c[1]), "f"(c[2]), "f"(c[3]));
}

DEVINL void cp_async16(void* smem, const void* gmem) {
    uint32_t s = (uint32_t)__cvta_generic_to_shared(smem);
    asm volatile("cp.async.cg.shared.global [%0], [%1], 16;" :: "r"(s), "l"(gmem));
}
DEVINL void cp_commit() { asm volatile("cp.async.commit_group;"); }
template<int N> DEVINL void cp_wait() { asm volatile("cp.async.wait_group %0;" :: "n"(N)); }

// ================================================================================
// GEMM: out = A[M,768] @ W[768,768]^T + bias
//   MODE 0: epilogue scatters to [B,H,N,64] head layout
//   MODE 1: plain row-major [M,768]
// BM=128, BN=128, BK=16, 256 threads (8 warps, 32x64 warp tiles), tf32 mma,
// 3-stage cp.async pipeline (dynamic smem), ONE __syncthreads per k-iter.
// ================================================================================
constexpr int G_LDA = 20;
constexpr int G_STAGE = 128 * G_LDA;                  // floats per matrix per stage
constexpr int SMEM_GEMM = 3 * 2 * G_STAGE * 4;        // 61440 B

template<int MODE>
__global__ __launch_bounds__(256)
void gemm_xwT(const float* __restrict__ A, const float* __restrict__ W,
              const float* __restrict__ bias, float* __restrict__ out) {
    constexpr int BM = 128, BN = 128, BK = 16, LDA = G_LDA, NK = Dd / BK;  // NK=48
    extern __shared__ float gsm[];
    float* Asm = gsm;
    float* Bsm = gsm + 3 * G_STAGE;

    const int tid = threadIdx.x;
    const int m0 = blockIdx.y * BM;
    const int n0 = blockIdx.x * BN;

    const int srow = tid >> 1;          // 0..127
    const int scol = (tid & 1) * 8;     // 0 or 8

    const int wid = tid >> 5, lane = tid & 31;
    const int wm = wid >> 1, wn = wid & 1;          // warp tile: rows wm*32, cols wn*64
    const int g = lane >> 2, t = lane & 3;

    float acc[2][8][4] = {};

    auto stage = [&](int buf, int k0) {
        float* As = Asm + buf * G_STAGE;
        float* Bs = Bsm + buf * G_STAGE;
        const float* ag = A + (size_t)(m0 + srow) * Dd + k0 + scol;
        cp_async16(As + srow * LDA + scol,     ag);
        cp_async16(As + srow * LDA + scol + 4, ag + 4);
        const float* bg = W + (size_t)(n0 + srow) * Dd + k0 + scol;
        cp_async16(Bs + srow * LDA + scol,     bg);
        cp_async16(Bs + srow * LDA + scol + 4, bg + 4);
        cp_commit();
    };

    stage(0, 0);
    stage(1, BK);

    for (int kt = 0; kt < NK; kt++) {
        if (kt + 1 < NK) cp_wait<1>(); else cp_wait<0>();
        __syncthreads();
        if (kt + 2 < NK) stage((kt + 2) % 3, (kt + 2) * BK);
        const int s = kt % 3;
        const float* As = Asm + s * G_STAGE;
        const float* Bs = Bsm + s * G_STAGE;
#pragma unroll
        for (int ks = 0; ks < 2; ks++) {
            uint32_t af[2][4], bf[8][2];
#pragma unroll
            for (int mt = 0; mt < 2; mt++) {
                const int rb = wm * 32 + mt * 16;
                af[mt][0] = f2tf32(As[(rb + g    ) * LDA + ks * 8 + t    ]);
                af[mt][1] = f2tf32(As[(rb + g + 8) * LDA + ks * 8 + t    ]);
                af[mt][2] = f2tf32(As[(rb + g    ) * LDA + ks * 8 + t + 4]);
                af[mt][3] = f2tf32(As[(rb + g + 8) * LDA + ks * 8 + t + 4]);
            }
#pragma unroll
            for (int nt = 0; nt < 8; nt++) {
                const int cb = wn * 64 + nt * 8;
                bf[nt][0] = f2tf32(Bs[(cb + g) * LDA + ks * 8 + t    ]);
                bf[nt][1] = f2tf32(Bs[(cb + g) * LDA + ks * 8 + t + 4]);
            }
#pragma unroll
            for (int mt = 0; mt < 2; mt++)
#pragma unroll
                for (int nt = 0; nt < 8; nt++)
                    mma_tf32(acc[mt][nt], af[mt], bf[nt], acc[mt][nt]);
        }
    }

    // epilogue
#pragma unroll
    for (int mt = 0; mt < 2; mt++) {
#pragma unroll
        for (int nt = 0; nt < 8; nt++) {
#pragma unroll
            for (int jr = 0; jr < 2; jr++) {
                const int m = m0 + wm * 32 + mt * 16 + g + jr * 8;
                const int c = n0 + wn * 64 + nt * 8 + t * 2;
                const float v0 = acc[mt][nt][jr * 2 + 0] + bias[c];
                const float v1 = acc[mt][nt][jr * 2 + 1] + bias[c + 1];
                if (MODE == 0) {
                    const int b = m >> 10, ns = m & 1023;
                    const int h = c >> 6,  hd = c & 63;
                    float* o = out + ((size_t)((b * Hh + h) * NSEQ + ns)) * HD + hd;
                    o[0] = v0; o[1] = v1;
                } else {
                    float* o = out + (size_t)m * Dd + c;
                    o[0] = v0; o[1] = v1;
                }
            }
        }
    }
}

// ================================================================================
// Fused attention (flash-style, tf32 mma), pipelined:
//   block = 256 threads (8 warps), q-tile = 128 rows (16 per warp), k-tile = 64.
//   cp.async DOUBLE-BUFFERED staging of K, V, bias, mask; one __syncthreads/tile.
//   Softmax exp on the FMA pipe (fexp), not MUFU.
//   K mma fragments fed as raw fp32 bits (HW tf32 truncation) — no cvt.
// ================================================================================
constexpr int LK = 68, LV = 72, LP = 68;
constexpr int SM_K = 2 * 64 * LK;     // floats
constexpr int SM_V = 2 * 64 * LV;
constexpr int SM_B = 2 * 128 * LP;
constexpr int SM_M = 2 * 128 * LP;    // ints
constexpr int SMEM_ATTN = (SM_K + SM_V + SM_B + SM_M) * 4;   // 210944 B

__global__ __launch_bounds__(256, 1)
void attn_fused(const float* __restrict__ qh, const float* __restrict__ kh,
                const float* __restrict__ vh, const float* __restrict__ bias,
                const int* __restrict__ mask, float* __restrict__ out) {
    extern __shared__ float sm[];
    float* Ks  = sm;                  // [2][64][LK]
    float* Vs  = sm + SM_K;           // [2][64][LV]
    float* Bsm = Vs + SM_V;           // [2][128][LP]  bias then P
    int*   Msm = (int*)(Bsm + SM_B);  // [2][128][LP]
    float* Qst = Bsm + 128 * LP;      // Q staging in Bsm buffer 1 (freed before tile 1)

    const int tid = threadIdx.x;
    const int w = tid >> 5, lane = tid & 31;
    const int g = lane >> 2, t = lane & 3;
    const int rb = w * 16;
    const int qt = blockIdx.x;        // 0..7
    const int bh = blockIdx.y;        // 0..95
    const int b = bh / Hh;
    const int h = bh - b * Hh;
    const int q0 = qt * 128;
    const size_t kvbase = (size_t)bh * NSEQ * HD;

    auto stage = [&](int buf, int kt) {
        const int k0 = kt * 64;
        const float* kg = kh + kvbase + (size_t)k0 * HD;
        const float* vg = vh + kvbase + (size_t)k0 * HD;
#pragma unroll
        for (int i = 0; i < 4; i++) {
            const int c = tid + i * 256;            // 0..1023
            const int r = c >> 4, c4 = c & 15;
            cp_async16(Ks + buf * 64 * LK + r * LK + c4 * 4, kg + r * HD + c4 * 4);
            cp_async16(Vs + buf * 64 * LV + r * LV + c4 * 4, vg + r * HD + c4 * 4);
        }
        const float* bg = bias + ((size_t)bh * NSEQ + q0) * NSEQ + k0;
        const int*   mg = mask + ((size_t)b * NSEQ + q0) * NSEQ + k0;
#pragma unroll
        for (int i = 0; i < 8; i++) {
            const int c = tid + i * 256;            // 0..2047
            const int r = c >> 4, c4 = c & 15;
            cp_async16(Bsm + buf * 128 * LP + r * LP + c4 * 4, bg + (size_t)r * NSEQ + c4 * 4);
            cp_async16(Msm + buf * 128 * LP + r * LP + c4 * 4, mg + (size_t)r * NSEQ + c4 * 4);
        }
        cp_commit();
    };

    stage(0, 0);   // first tile in flight behind Q setup

    // ---- stage Q tile (scaled by 1/8) into Qst
    {
        const float4* qg = reinterpret_cast<const float4*>(qh + ((size_t)bh * NSEQ + q0) * HD);
#pragma unroll
        for (int i = 0; i < 8; i++) {
            const int idx = tid + i * 256;          // 0..2047
            const int r = idx >> 4, c4 = idx & 15;
            const float4 v = qg[idx];
            float* dst = Qst + r * LP + c4 * 4;
            dst[0] = v.x * 0.125f; dst[1] = v.y * 0.125f;
            dst[2] = v.z * 0.125f; dst[3] = v.w * 0.125f;
        }
    }
    __syncthreads();

    uint32_t qf[8][4];
#pragma unroll
    for (int ks = 0; ks < 8; ks++) {
        qf[ks][0] = f2tf32(Qst[(rb + g    ) * LP + ks * 8 + t    ]);
        qf[ks][1] = f2tf32(Qst[(rb + g + 8) * LP + ks * 8 + t    ]);
        qf[ks][2] = f2tf32(Qst[(rb + g    ) * LP + ks * 8 + t + 4]);
        qf[ks][3] = f2tf32(Qst[(rb + g + 8) * LP + ks * 8 + t + 4]);
    }

    float Of[8][4] = {};
    float m_lo = -INFINITY, m_hi = -INFINITY, l_lo = 0.f, l_hi = 0.f;

    for (int kt = 0; kt < 16; kt++) {
        const int buf = kt & 1;
        cp_wait<0>();
        __syncthreads();                       // tile kt visible; all done with kt-1
        if (kt + 1 < 16) stage(buf ^ 1, kt + 1);   // prefetch behind compute

        float* Kb  = Ks  + buf * 64 * LK;
        float* Vb  = Vs  + buf * 64 * LV;
        float* Bb2 = Bsm + buf * 128 * LP;
        int*   Mb  = Msm + buf * 128 * LP;

        // ---- S = Q @ K^T, then +bias / mask
        float sacc[8][4] = {};
#pragma unroll
        for (int nt = 0; nt < 8; nt++) {
            const int cb = nt * 8;
#pragma unroll
            for (int ks = 0; ks < 8; ks++) {
                uint32_t bf[2];
                bf[0] = __float_as_uint(Kb[(cb + g) * LK + ks * 8 + t    ]);  // HW tf32 truncation
                bf[1] = __float_as_uint(Kb[(cb + g) * LK + ks * 8 + t + 4]);
                mma_tf32(sacc[nt], qf[ks], bf, sacc[nt]);
            }
            const int r0 = rb + g;
            const int c = cb + t * 2;
            const int m0i = Mb[ r0      * LP + c    ];
            const int m1i = Mb[ r0      * LP + c + 1];
            const int m2i = Mb[(r0 + 8) * LP + c    ];
            const int m3i = Mb[(r0 + 8) * LP + c + 1];
            sacc[nt][0] = m0i ? sacc[nt][0] + Bb2[ r0      * LP + c    ] : -1e30f;
            sacc[nt][1] = m1i ? sacc[nt][1] + Bb2[ r0      * LP + c + 1] : -1e30f;
            sacc[nt][2] = m2i ? sacc[nt][2] + Bb2[(r0 + 8) * LP + c    ] : -1e30f;
            sacc[nt][3] = m3i ? sacc[nt][3] + Bb2[(r0 + 8) * LP + c + 1] : -1e30f;
        }

        // ---- online softmax (rows in 4-lane groups), exp on FMA pipe
        float mx_lo = -INFINITY, mx_hi = -INFINITY;
#pragma unroll
        for (int nt = 0; nt < 8; nt++) {
            mx_lo = fmaxf(mx_lo, fmaxf(sacc[nt][0], sacc[nt][1]));
            mx_hi = fmaxf(mx_hi, fmaxf(sacc[nt][2], sacc[nt][3]));
        }
        mx_lo = fmaxf(mx_lo, __shfl_xor_sync(0xffffffffu, mx_lo, 1));
        mx_lo = fmaxf(mx_lo, __shfl_xor_sync(0xffffffffu, mx_lo, 2));
        mx_hi = fmaxf(mx_hi, __shfl_xor_sync(0xffffffffu, mx_hi, 1));
        mx_hi = fmaxf(mx_hi, __shfl_xor_sync(0xffffffffu, mx_hi, 2));
        const float mn_lo = fmaxf(m_lo, mx_lo), mn_hi = fmaxf(m_hi, mx_hi);
        const float corr_lo = fexp(m_lo - mn_lo), corr_hi = fexp(m_hi - mn_hi);
        float sum_lo = 0.f, sum_hi = 0.f;
        const int r0 = rb + g;
#pragma unroll
        for (int nt = 0; nt < 8; nt++) {
            const float p0 = fexp(sacc[nt][0] - mn_lo);
            const float p1 = fexp(sacc[nt][1] - mn_lo);
            const float p2 = fexp(sacc[nt][2] - mn_hi);
            const float p3 = fexp(sacc[nt][3] - mn_hi);
            sum_lo += p0 + p1; sum_hi += p2 + p3;
            Bb2[ r0      * LP + nt * 8 + t * 2    ] = p0;
            Bb2[ r0      * LP + nt * 8 + t * 2 + 1] = p1;
            Bb2[(r0 + 8) * LP + nt * 8 + t * 2    ] = p2;
            Bb2[(r0 + 8) * LP + nt * 8 + t * 2 + 1] = p3;
        }
        sum_lo += __shfl_xor_sync(0xffffffffu, sum_lo, 1);
        sum_lo += __shfl_xor_sync(0xffffffffu, sum_lo, 2);
        sum_hi += __shfl_xor_sync(0xffffffffu, sum_hi, 1);
        sum_hi += __shfl_xor_sync(0xffffffffu, sum_hi, 2);
        l_lo = l_lo * corr_lo + sum_lo;
        l_hi = l_hi * corr_hi + sum_hi;
        m_lo = mn_lo; m_hi = mn_hi;
#pragma unroll
        for (int n2 = 0; n2 < 8; n2++) {
            Of[n2][0] *= corr_lo; Of[n2][1] *= corr_lo;
            Of[n2][2] *= corr_hi; Of[n2][3] *= corr_hi;
        }
        __syncwarp();   // P stores visible within warp before fragment loads

        // ---- O += P @ V  (16 x 64 per warp, K=64)
#pragma unroll
        for (int ks2 = 0; ks2 < 8; ks2++) {
            uint32_t af[4];
            af[0] = f2tf32(Bb2[(rb + g    ) * LP + ks2 * 8 + t    ]);
            af[1] = f2tf32(Bb2[(rb + g + 8) * LP + ks2 * 8 + t    ]);
            af[2] = f2tf32(Bb2[(rb + g    ) * LP + ks2 * 8 + t + 4]);
            af[3] = f2tf32(Bb2[(rb + g + 8) * LP + ks2 * 8 + t + 4]);
#pragma unroll
            for (int n2 = 0; n2 < 8; n2++) {
                uint32_t bf[2];
                bf[0] = f2tf32(Vb[(ks2 * 8 + t    ) * LV + n2 * 8 + g]);
                bf[1] = f2tf32(Vb[(ks2 * 8 + t + 4) * LV + n2 * 8 + g]);
                mma_tf32(Of[n2], af, bf, Of[n2]);
            }
        }
    }

    // ---- epilogue: normalize and write [B,N,D]
    const float il_lo = 1.f / l_lo, il_hi = 1.f / l_hi;
    float* ob = out + ((size_t)(b * NSEQ) + q0) * Dd + h * HD;
#pragma unroll
    for (int n2 = 0; n2 < 8; n2++) {
        const int r = rb + g;
        const int c = n2 * 8 + t * 2;
        ob[(size_t)r * Dd + c    ]       = Of[n2][0] * il_lo;
        ob[(size_t)r * Dd + c + 1]       = Of[n2][1] * il_lo;
        ob[(size_t)(r + 8) * Dd + c    ] = Of[n2][2] * il_hi;
        ob[(size_t)(r + 8) * Dd + c + 1] = Of[n2][3] * il_hi;
    }
}

// ================================================================================
extern "C" void kernel_launch(void* const* d_in, const int* /*in_sizes*/, int /*n_in*/,
                              void* d_out, int /*out_size*/) {
    const float* q    = (const float*)d_in[0];
    const float* k    = (const float*)d_in[1];
    const float* v    = (const float*)d_in[2];
    const float* bias = (const float*)d_in[3];
    const int*   mask = (const int*)  d_in[4];
    const float* Wq   = (const float*)d_in[5];
    const float* bq   = (const float*)d_in[6];
    const float* Wk   = (const float*)d_in[7];
    const float* bk   = (const float*)d_in[8];
    const float* Wv   = (const float*)d_in[9];
    const float* bv   = (const float*)d_in[10];
    const float* Wo   = (const float*)d_in[11];
    const float* bo   = (const float*)d_in[12];

    float *pqh, *pkh, *pvh, *pao;
    cudaGetSymbolAddress((void**)&pqh, g_qh);
    cudaGetSymbolAddress((void**)&pkh, g_kh);
    cudaGetSymbolAddress((void**)&pvh, g_vh);
    cudaGetSymbolAddress((void**)&pao, g_ao);

    cudaFuncSetAttribute(gemm_xwT<0>, cudaFuncAttributeMaxDynamicSharedMemorySize, SMEM_GEMM);
    cudaFuncSetAttribute(gemm_xwT<1>, cudaFuncAttributeMaxDynamicSharedMemorySize, SMEM_GEMM);
    cudaFuncSetAttribute(attn_fused, cudaFuncAttributeMaxDynamicSharedMemorySize, SMEM_ATTN);

    const dim3 gg(Dd / 128, Mrows / 128);   // (6, 64)
    gemm_xwT<0><<<gg, 256, SMEM_GEMM>>>(q, Wq, bq, pqh);
    gemm_xwT<0><<<gg, 256, SMEM_GEMM>>>(k, Wk, bk, pkh);
    gemm_xwT<0><<<gg, 256, SMEM_GEMM>>>(v, Wv, bv, pvh);

    attn_fused<<<dim3(NSEQ / 128, Bb * Hh), 256, SMEM_ATTN>>>(pqh, pkh, pvh, bias, mask, pao);

    gemm_xwT<1><<<gg, 256, SMEM_GEMM>>>(pao, Wo, bo, (float*)d_out);
}

// round 6
// speedup vs baseline: 1.7570x; 1.7570x over previous
#include <cuda_runtime.h>
#include <cuda_fp16.h>
#include <cstdint>
#include <cstddef>

#define DEVINL __device__ __forceinline__

constexpr int Bb   = 8;
constexpr int NSEQ = 1024;
constexpr int Dd   = 768;
constexpr int Hh   = 12;
constexpr int HD   = 64;
constexpr int Mrows = Bb * NSEQ;   // 8192
constexpr int DD2  = Dd * Dd;

// ---------------- scratch (allocation-free rule: __device__ globals) ----------
__device__ __align__(128) __half g_hq[(size_t)Mrows * Dd];     // fp16 inputs
__device__ __align__(128) __half g_hk[(size_t)Mrows * Dd];
__device__ __align__(128) __half g_hv[(size_t)Mrows * Dd];
__device__ __align__(128) __half g_hw[(size_t)4 * DD2];        // fp16 Wq,Wk,Wv,Wo
__device__ __align__(128) __half g_qh[(size_t)Bb * Hh * NSEQ * HD];  // [B,H,N,64] (pre-scaled 1/8)
__device__ __align__(128) __half g_kh[(size_t)Bb * Hh * NSEQ * HD];  // [B,H,N,64]
__device__ __align__(128) __half g_vt[(size_t)Bb * Hh * HD * NSEQ];  // [B,H,64,N] transposed
__device__ __align__(128) __half g_ao[(size_t)Mrows * Dd];           // attention out [B,N,D]

// ---------------- helpers ------------------------------------------------------
DEVINL void mma_f16(float d[4], const uint32_t a[4], const uint32_t b[2], const float c[4]) {
    asm("mma.sync.aligned.m16n8k16.row.col.f32.f16.f16.f32 "
        "{%0,%1,%2,%3}, {%4,%5,%6,%7}, {%8,%9}, {%10,%11,%12,%13};"
        : "=f"(d[0]), "=f"(d[1]), "=f"(d[2]), "=f"(d[3])
        : "r"(a[0]), "r"(a[1]), "r"(a[2]), "r"(a[3]),
          "r"(b[0]), "r"(b[1]),
          "f"(c[0]), "f"(c[1]), "f"(c[2]), "f"(c[3]));
}

DEVINL void cp_async16(void* smem, const void* gmem) {
    uint32_t s = (uint32_t)__cvta_generic_to_shared(smem);
    asm volatile("cp.async.cg.shared.global [%0], [%1], 16;" :: "r"(s), "l"(gmem));
}
DEVINL void cp_commit() { asm volatile("cp.async.commit_group;"); }
template<int N> DEVINL void cp_wait() { asm volatile("cp.async.wait_group %0;" :: "n"(N)); }

// ================================================================================
// fp32 -> fp16 conversion kernels
// ================================================================================
__global__ __launch_bounds__(256)
void cvt_qkv(const float* __restrict__ a, const float* __restrict__ b, const float* __restrict__ c,
             __half* __restrict__ oa, __half* __restrict__ ob, __half* __restrict__ oc) {
    const float4* s = reinterpret_cast<const float4*>(blockIdx.z == 0 ? a : blockIdx.z == 1 ? b : c);
    __half2* d = reinterpret_cast<__half2*>(blockIdx.z == 0 ? oa : blockIdx.z == 1 ? ob : oc);
    const int i = blockIdx.x * 256 + threadIdx.x;
    const float4 v = s[i];
    d[2 * i]     = __floats2half2_rn(v.x, v.y);
    d[2 * i + 1] = __floats2half2_rn(v.z, v.w);
}

__global__ __launch_bounds__(256)
void cvt_w(const float* __restrict__ w0, const float* __restrict__ w1,
           const float* __restrict__ w2, const float* __restrict__ w3,
           __half* __restrict__ out) {
    const float* src = blockIdx.z == 0 ? w0 : blockIdx.z == 1 ? w1 : blockIdx.z == 2 ? w2 : w3;
    const float4* s = reinterpret_cast<const float4*>(src);
    __half2* d = reinterpret_cast<__half2*>(out + (size_t)blockIdx.z * DD2);
    const int i = blockIdx.x * 256 + threadIdx.x;
    const float4 v = s[i];
    d[2 * i]     = __floats2half2_rn(v.x, v.y);
    d[2 * i + 1] = __floats2half2_rn(v.z, v.w);
}

// ================================================================================
// fp16 GEMM: out = (A[M,768] @ W[768,768]^T + bias) * scale
//   MODE 0: half out, head layout [B,H,N,64]
//   MODE 2: half out, transposed head layout [B,H,64,N]   (for V)
//   MODE 1: fp32 out, row-major [M,768]                    (final O-proj)
// BM=128, BN=128, BK=32, 256 threads (8 warps, 32x64 tiles), m16n8k16,
// 3-stage cp.async pipeline. Smem rows 40 halfs (bank-conflict-free frag LDS).
// ================================================================================
constexpr int GLH   = 40;                  // halfs per smem row
constexpr int G_STGB = 128 * GLH * 2;      // 10240 B per matrix-stage
constexpr int SMEM_G = 3 * 2 * G_STGB;     // 61440 B

template<int MODE>
__global__ __launch_bounds__(256)
void hgemm(const __half* __restrict__ A, const __half* __restrict__ W,
           const float* __restrict__ bias, void* __restrict__ out, float scale) {
    constexpr int BK = 32, NK = Dd / BK;   // 24
    extern __shared__ __align__(16) uint8_t gsm[];
    uint8_t* stA = gsm;
    uint8_t* stB = gsm + 3 * G_STGB;

    const int tid = threadIdx.x;
    const int m0 = blockIdx.y * 128;
    const int n0 = blockIdx.x * 128;

    const int wid = tid >> 5, lane = tid & 31;
    const int wm = wid >> 1, wn = wid & 1;
    const int g = lane >> 2, t = lane & 3;

    float acc[2][8][4] = {};

    auto stage = [&](int s, int ki) {
        const int k0 = ki * BK;
#pragma unroll
        for (int i = 0; i < 2; i++) {
            const int idx = tid + i * 256;          // 0..511
            const int r = idx >> 2, cc = idx & 3;   // row, 16B chunk (8 halfs)
            cp_async16(stA + s * G_STGB + r * 80 + cc * 16, A + (size_t)(m0 + r) * Dd + k0 + cc * 8);
            cp_async16(stB + s * G_STGB + r * 80 + cc * 16, W + (size_t)(n0 + r) * Dd + k0 + cc * 8);
        }
        cp_commit();
    };

    stage(0, 0);
    stage(1, 1);

    for (int kt = 0; kt < NK; kt++) {
        if (kt + 1 < NK) cp_wait<1>(); else cp_wait<0>();
        __syncthreads();
        if (kt + 2 < NK) stage((kt + 2) % 3, kt + 2);
        const int s = kt % 3;
        const uint32_t* As32 = reinterpret_cast<const uint32_t*>(stA + s * G_STGB);
        const uint32_t* Bs32 = reinterpret_cast<const uint32_t*>(stB + s * G_STGB);
#pragma unroll
        for (int ks = 0; ks < 2; ks++) {           // two k16 steps
            uint32_t af[2][4], bf[8][2];
#pragma unroll
            for (int mt = 0; mt < 2; mt++) {
                const int rb = wm * 32 + mt * 16;
                af[mt][0] = As32[(rb + g    ) * 20 + ks * 8 + t    ];
                af[mt][1] = As32[(rb + g + 8) * 20 + ks * 8 + t    ];
                af[mt][2] = As32[(rb + g    ) * 20 + ks * 8 + t + 4];
                af[mt][3] = As32[(rb + g + 8) * 20 + ks * 8 + t + 4];
            }
#pragma unroll
            for (int nt = 0; nt < 8; nt++) {
                const int cb = wn * 64 + nt * 8;
                bf[nt][0] = Bs32[(cb + g) * 20 + ks * 8 + t    ];
                bf[nt][1] = Bs32[(cb + g) * 20 + ks * 8 + t + 4];
            }
#pragma unroll
            for (int mt = 0; mt < 2; mt++)
#pragma unroll
                for (int nt = 0; nt < 8; nt++)
                    mma_f16(acc[mt][nt], af[mt], bf[nt], acc[mt][nt]);
        }
        __syncthreads();
    }

    // epilogue
#pragma unroll
    for (int mt = 0; mt < 2; mt++) {
#pragma unroll
        for (int nt = 0; nt < 8; nt++) {
#pragma unroll
            for (int jr = 0; jr < 2; jr++) {
                const int m = m0 + wm * 32 + mt * 16 + g + jr * 8;
                const int c = n0 + wn * 64 + nt * 8 + t * 2;
                const float v0 = (acc[mt][nt][jr * 2 + 0] + bias[c])     * scale;
                const float v1 = (acc[mt][nt][jr * 2 + 1] + bias[c + 1]) * scale;
                if (MODE == 0) {
                    const int b = m >> 10, ns = m & 1023;
                    const int h = c >> 6, hd = c & 63;
                    __half* o = (__half*)out + ((size_t)((b * Hh + h) * NSEQ + ns)) * HD + hd;
                    *reinterpret_cast<__half2*>(o) = __floats2half2_rn(v0, v1);
                } else if (MODE == 2) {
                    const int b = m >> 10, ns = m & 1023;
                    const int h = c >> 6, hd = c & 63;
                    __half* o = (__half*)out + ((size_t)(b * Hh + h) * HD + hd) * NSEQ + ns;
                    o[0]    = __float2half_rn(v0);
                    o[NSEQ] = __float2half_rn(v1);
                } else {
                    float* o = (float*)out + (size_t)m * Dd + c;
                    o[0] = v0; o[1] = v1;
                }
            }
        }
    }
}

// ================================================================================
// Fused attention (flash-style, fp16 m16n8k16), cp.async double-buffered.
//   block = 256 threads (8 warps), q-tile = 128 (16/warp), k-tile = 64.
//   Q [B,H,N,64] half pre-scaled by 1/8. V comes transposed [B,H,64,N].
//   bias/mask fp32/int32 in smem; S accum fp32; P->half2 in smem; O accum fp32.
// ================================================================================
constexpr int LKH = 72;                       // halfs/row, K & Vt & P & Qst
constexpr int LPF = 68;                       // floats/row, bias & mask
constexpr int KT_B  = 64 * LKH * 2;           // 9216 B (one K or Vt tile)
constexpr int BM_B  = 128 * LPF * 4;          // 34816 B (one bias or mask tile)
constexpr int OFF_K  = 0;
constexpr int OFF_VT = OFF_K  + 2 * KT_B;     // 18432
constexpr int OFF_BI = OFF_VT + 2 * KT_B;     // 36864
constexpr int OFF_MA = OFF_BI + 2 * BM_B;     // 106496
constexpr int OFF_P  = OFF_MA + 2 * BM_B;     // 176128
constexpr int SMEM_ATTN = OFF_P + 128 * LKH * 2;   // 194560 B

__global__ __launch_bounds__(256, 1)
void attn_fused(const __half* __restrict__ qh, const __half* __restrict__ kh,
                const __half* __restrict__ vt, const float* __restrict__ bias,
                const int* __restrict__ mask, __half* __restrict__ out) {
    extern __shared__ __align__(16) uint8_t sm[];

    const int tid = threadIdx.x;
    const int w = tid >> 5, lane = tid & 31;
    const int g = lane >> 2, t = lane & 3;
    const int rb = w * 16;
    const int qt = blockIdx.x;        // 0..7
    const int bh = blockIdx.y;        // 0..95
    const int b = bh / Hh;
    const int h = bh - b * Hh;
    const int q0 = qt * 128;
    const size_t kvbase = (size_t)bh * NSEQ * HD;

    auto stage = [&](int buf, int kt) {
        const int k0 = kt * 64;
        const __half* kg = kh + kvbase + (size_t)k0 * HD;              // [kpos][64]
        const __half* vg = vt + (size_t)bh * HD * NSEQ + k0;           // [hd][kpos]
#pragma unroll
        for (int i = 0; i < 2; i++) {
            const int c = tid + i * 256;          // 0..511
            const int r = c >> 3, cc = c & 7;
            cp_async16(sm + OFF_K  + buf * KT_B + r * 144 + cc * 16, kg + (size_t)r * HD   + cc * 8);
            cp_async16(sm + OFF_VT + buf * KT_B + r * 144 + cc * 16, vg + (size_t)r * NSEQ + cc * 8);
        }
        const float* bg = bias + ((size_t)bh * NSEQ + q0) * NSEQ + k0;
        const int*   mg = mask + ((size_t)b * NSEQ + q0) * NSEQ + k0;
#pragma unroll
        for (int i = 0; i < 8; i++) {
            const int c = tid + i * 256;          // 0..2047
            const int r = c >> 4, c4 = c & 15;
            cp_async16(sm + OFF_BI + buf * BM_B + r * LPF * 4 + c4 * 16, bg + (size_t)r * NSEQ + c4 * 4);
            cp_async16(sm + OFF_MA + buf * BM_B + r * LPF * 4 + c4 * 16, mg + (size_t)r * NSEQ + c4 * 4);
        }
        cp_commit();
    };

    stage(0, 0);

    // ---- stage Q tile (already 1/8-scaled) into P area
    {
        const __half* qg = qh + ((size_t)bh * NSEQ + q0) * HD;
#pragma unroll
        for (int i = 0; i < 4; i++) {
            const int idx = tid + i * 256;        // 0..1023
            const int r = idx >> 3, cc = idx & 7;
            cp_async16(sm + OFF_P + r * 144 + cc * 16, qg + (size_t)r * HD + cc * 8);
        }
        cp_commit();
    }
    cp_wait<0>();
    __syncthreads();

    uint32_t qf[4][4];
    {
        const uint32_t* Q32 = reinterpret_cast<const uint32_t*>(sm + OFF_P);
#pragma unroll
        for (int ks = 0; ks < 4; ks++) {
            qf[ks][0] = Q32[(rb + g    ) * 36 + ks * 8 + t    ];
            qf[ks][1] = Q32[(rb + g + 8) * 36 + ks * 8 + t    ];
            qf[ks][2] = Q32[(rb + g    ) * 36 + ks * 8 + t + 4];
            qf[ks][3] = Q32[(rb + g + 8) * 36 + ks * 8 + t + 4];
        }
    }

    float Of[8][4] = {};
    float m_lo = -INFINITY, m_hi = -INFINITY, l_lo = 0.f, l_hi = 0.f;

    for (int kt = 0; kt < 16; kt++) {
        const int buf = kt & 1;
        if (kt > 0) { cp_wait<0>(); __syncthreads(); }
        if (kt + 1 < 16) stage(buf ^ 1, kt + 1);   // prefetch behind compute

        const uint32_t* K32  = reinterpret_cast<const uint32_t*>(sm + OFF_K  + buf * KT_B);
        const uint32_t* Vt32 = reinterpret_cast<const uint32_t*>(sm + OFF_VT + buf * KT_B);
        const float*    Bf   = reinterpret_cast<const float*>   (sm + OFF_BI + buf * BM_B);
        const int*      Mi   = reinterpret_cast<const int*>     (sm + OFF_MA + buf * BM_B);
        uint32_t*       P32  = reinterpret_cast<uint32_t*>      (sm + OFF_P);

        // ---- S = Q @ K^T (fp32 acc), then +bias / mask
        float sacc[8][4] = {};
#pragma unroll
        for (int nt = 0; nt < 8; nt++) {
            const int cb = nt * 8;
#pragma unroll
            for (int ks = 0; ks < 4; ks++) {
                uint32_t bf[2];
                bf[0] = K32[(cb + g) * 36 + ks * 8 + t    ];
                bf[1] = K32[(cb + g) * 36 + ks * 8 + t + 4];
                mma_f16(sacc[nt], qf[ks], bf, sacc[nt]);
            }
            const int r0 = rb + g;
            const int c = cb + t * 2;
            const int m0i = Mi[ r0      * LPF + c    ];
            const int m1i = Mi[ r0      * LPF + c + 1];
            const int m2i = Mi[(r0 + 8) * LPF + c    ];
            const int m3i = Mi[(r0 + 8) * LPF + c + 1];
            sacc[nt][0] = m0i ? sacc[nt][0] + Bf[ r0      * LPF + c    ] : -1e30f;
            sacc[nt][1] = m1i ? sacc[nt][1] + Bf[ r0      * LPF + c + 1] : -1e30f;
            sacc[nt][2] = m2i ? sacc[nt][2] + Bf[(r0 + 8) * LPF + c    ] : -1e30f;
            sacc[nt][3] = m3i ? sacc[nt][3] + Bf[(r0 + 8) * LPF + c + 1] : -1e30f;
        }

        // ---- online softmax (rows in 4-lane groups)
        float mx_lo = -INFINITY, mx_hi = -INFINITY;
#pragma unroll
        for (int nt = 0; nt < 8; nt++) {
            mx_lo = fmaxf(mx_lo, fmaxf(sacc[nt][0], sacc[nt][1]));
            mx_hi = fmaxf(mx_hi, fmaxf(sacc[nt][2], sacc[nt][3]));
        }
        mx_lo = fmaxf(mx_lo, __shfl_xor_sync(0xffffffffu, mx_lo, 1));
        mx_lo = fmaxf(mx_lo, __shfl_xor_sync(0xffffffffu, mx_lo, 2));
        mx_hi = fmaxf(mx_hi, __shfl_xor_sync(0xffffffffu, mx_hi, 1));
        mx_hi = fmaxf(mx_hi, __shfl_xor_sync(0xffffffffu, mx_hi, 2));
        const float mn_lo = fmaxf(m_lo, mx_lo), mn_hi = fmaxf(m_hi, mx_hi);
        const float corr_lo = __expf(m_lo - mn_lo), corr_hi = __expf(m_hi - mn_hi);
        float sum_lo = 0.f, sum_hi = 0.f;
        const int r0 = rb + g;
#pragma unroll
        for (int nt = 0; nt < 8; nt++) {
            const float p0 = __expf(sacc[nt][0] - mn_lo);
            const float p1 = __expf(sacc[nt][1] - mn_lo);
            const float p2 = __expf(sacc[nt][2] - mn_hi);
            const float p3 = __expf(sacc[nt][3] - mn_hi);
            sum_lo += p0 + p1; sum_hi += p2 + p3;
            const __half2 h01 = __floats2half2_rn(p0, p1);
            const __half2 h23 = __floats2half2_rn(p2, p3);
            P32[ r0      * 36 + nt * 4 + t] = *reinterpret_cast<const uint32_t*>(&h01);
            P32[(r0 + 8) * 36 + nt * 4 + t] = *reinterpret_cast<const uint32_t*>(&h23);
        }
        sum_lo += __shfl_xor_sync(0xffffffffu, sum_lo, 1);
        sum_lo += __shfl_xor_sync(0xffffffffu, sum_lo, 2);
        sum_hi += __shfl_xor_sync(0xffffffffu, sum_hi, 1);
        sum_hi += __shfl_xor_sync(0xffffffffu, sum_hi, 2);
        l_lo = l_lo * corr_lo + sum_lo;
        l_hi = l_hi * corr_hi + sum_hi;
        m_lo = mn_lo; m_hi = mn_hi;
#pragma unroll
        for (int n2 = 0; n2 < 8; n2++) {
            Of[n2][0] *= corr_lo; Of[n2][1] *= corr_lo;
            Of[n2][2] *= corr_hi; Of[n2][3] *= corr_hi;
        }
        __syncwarp();   // P stores visible within warp before fragment loads

        // ---- O += P @ V  (16 x 64 per warp, K=64 via 4 k16 steps)
#pragma unroll
        for (int ks2 = 0; ks2 < 4; ks2++) {
            uint32_t af[4];
            af[0] = P32[(rb + g    ) * 36 + ks2 * 8 + t    ];
            af[1] = P32[(rb + g + 8) * 36 + ks2 * 8 + t    ];
            af[2] = P32[(rb + g    ) * 36 + ks2 * 8 + t + 4];
            af[3] = P32[(rb + g + 8) * 36 + ks2 * 8 + t + 4];
#pragma unroll
            for (int n2 = 0; n2 < 8; n2++) {
                uint32_t bf[2];
                bf[0] = Vt32[(n2 * 8 + g) * 36 + ks2 * 8 + t    ];
                bf[1] = Vt32[(n2 * 8 + g) * 36 + ks2 * 8 + t + 4];
                mma_f16(Of[n2], af, bf, Of[n2]);
            }
        }
    }

    // ---- epilogue: normalize, write half [B,N,D]
    const float il_lo = 1.f / l_lo, il_hi = 1.f / l_hi;
    __half* ob = out + ((size_t)(b * NSEQ) + q0) * Dd + h * HD;
#pragma unroll
    for (int n2 = 0; n2 < 8; n2++) {
        const int r = rb + g;
        const int c = n2 * 8 + t * 2;
        *reinterpret_cast<__half2*>(ob + (size_t)r * Dd + c) =
            __floats2half2_rn(Of[n2][0] * il_lo, Of[n2][1] * il_lo);
        *reinterpret_cast<__half2*>(ob + (size_t)(r + 8) * Dd + c) =
            __floats2half2_rn(Of[n2][2] * il_hi, Of[n2][3] * il_hi);
    }
}

// ================================================================================
extern "C" void kernel_launch(void* const* d_in, const int* /*in_sizes*/, int /*n_in*/,
                              void* d_out, int /*out_size*/) {
    const float* q    = (const float*)d_in[0];
    const float* k    = (const float*)d_in[1];
    const float* v    = (const float*)d_in[2];
    const float* bias = (const float*)d_in[3];
    const int*   mask = (const int*)  d_in[4];
    const float* Wq   = (const float*)d_in[5];
    const float* bq   = (const float*)d_in[6];
    const float* Wk   = (const float*)d_in[7];
    const float* bk   = (const float*)d_in[8];
    const float* Wv   = (const float*)d_in[9];
    const float* bv   = (const float*)d_in[10];
    const float* Wo   = (const float*)d_in[11];
    const float* bo   = (const float*)d_in[12];

    __half *phq, *phk, *phv, *phw, *pqh, *pkh, *pvt, *pao;
    cudaGetSymbolAddress((void**)&phq, g_hq);
    cudaGetSymbolAddress((void**)&phk, g_hk);
    cudaGetSymbolAddress((void**)&phv, g_hv);
    cudaGetSymbolAddress((void**)&phw, g_hw);
    cudaGetSymbolAddress((void**)&pqh, g_qh);
    cudaGetSymbolAddress((void**)&pkh, g_kh);
    cudaGetSymbolAddress((void**)&pvt, g_vt);
    cudaGetSymbolAddress((void**)&pao, g_ao);

    cudaFuncSetAttribute(hgemm<0>, cudaFuncAttributeMaxDynamicSharedMemorySize, SMEM_G);
    cudaFuncSetAttribute(hgemm<1>, cudaFuncAttributeMaxDynamicSharedMemorySize, SMEM_G);
    cudaFuncSetAttribute(hgemm<2>, cudaFuncAttributeMaxDynamicSharedMemorySize, SMEM_G);
    cudaFuncSetAttribute(attn_fused, cudaFuncAttributeMaxDynamicSharedMemorySize, SMEM_ATTN);

    // 1) fp32 -> fp16 conversion
    cvt_qkv<<<dim3(Mrows * Dd / 4 / 256, 1, 3), 256>>>(q, k, v, phq, phk, phv);
    cvt_w  <<<dim3(DD2 / 4 / 256, 1, 4), 256>>>(Wq, Wk, Wv, Wo, phw);

    // 2) fp16 projections (Q pre-scaled by 1/8; V transposed)
    const dim3 gg(Dd / 128, Mrows / 128);   // (6, 64)
    hgemm<0><<<gg, 256, SMEM_G>>>(phq, phw,           bq, pqh, 0.125f);
    hgemm<0><<<gg, 256, SMEM_G>>>(phk, phw + DD2,     bk, pkh, 1.0f);
    hgemm<2><<<gg, 256, SMEM_G>>>(phv, phw + 2 * DD2, bv, pvt, 1.0f);

    // 3) fused attention
    attn_fused<<<dim3(NSEQ / 128, Bb * Hh), 256, SMEM_ATTN>>>(pqh, pkh, pvt, bias, mask, pao);

    // 4) O projection (fp32 out)
    hgemm<1><<<gg, 256, SMEM_G>>>(pao, phw + 3 * DD2, bo, d_out, 1.0f);
}